// round 16
// baseline (speedup 1.0000x reference)
#include <cuda_runtime.h>
#include <cuda_bf16.h>
#include <cstdint>

#define N_NODES 100000
#define N_EDGES 3200000
#define BN_EPS 1e-5f
#define SLOPE 0.01f
#define SCAN_CHUNK 512
#define SCAN_NB ((N_NODES + SCAN_CHUNK - 1) / SCAN_CHUNK)
#define SROW 40   // smem row stride (bf16): 80B, 16B-aligned, ldsm conflict-free (validated R12/R15)

// ---------------- scratch (static device globals; no allocation) ----------------
__device__ unsigned char g_arena[(size_t)N_NODES * 1024 * 2];  // 204.8 MB
__device__ float g_dinv[N_NODES];
__device__ int   g_cnt [N_NODES];
__device__ int   g_fill[N_NODES];
__device__ int   g_rowptr[N_NODES];
__device__ int   g_blocksums[SCAN_NB];
__device__ int   g_src[N_EDGES];
__device__ int   g_dst[N_EDGES];
__device__ int   g_csrc[N_EDGES];
__device__ int   g_is64;
__device__ float g_h1 [(size_t)N_NODES * 256];
__device__ float g_h2 [(size_t)N_NODES * 512];
__device__ __nv_bfloat16 g_wd [(size_t)4096 * 1024];
__device__ __nv_bfloat16 g_w1s[(size_t)256 * 256];
__device__ __nv_bfloat16 g_w2s[(size_t)512 * 512];
__device__ float g_logits[(size_t)N_NODES * 6];
__device__ float g_colsum[512];
__device__ float g_colsq [512];
__device__ float g_scale [512];
__device__ float g_shift [512];

// ---------------- cp.async / ldmatrix helpers ----------------
__device__ __forceinline__ void cpa16(uint32_t dst, const void* src, int srcsize) {
    asm volatile("cp.async.cg.shared.global [%0], [%1], 16, %2;"
                 :: "r"(dst), "l"(src), "r"(srcsize));
}
__device__ __forceinline__ void cpa_commit() { asm volatile("cp.async.commit_group;"); }
template <int N>
__device__ __forceinline__ void cpa_wait() { asm volatile("cp.async.wait_group %0;" :: "n"(N)); }
__device__ __forceinline__ void ldsm_x4(uint32_t& r0, uint32_t& r1, uint32_t& r2, uint32_t& r3,
                                        uint32_t addr) {
    asm volatile("ldmatrix.sync.aligned.m8n8.x4.shared.b16 {%0,%1,%2,%3}, [%4];"
                 : "=r"(r0), "=r"(r1), "=r"(r2), "=r"(r3) : "r"(addr));
}

// ---------------- edge dtype detection + conversion ----------------
__global__ void detect_k(const unsigned long long* __restrict__ p) {
    __shared__ int bad;
    if (threadIdx.x == 0) bad = 0;
    __syncthreads();
    for (int i = threadIdx.x; i < 4096; i += 256)
        if (p[i] >= (unsigned long long)N_NODES) bad = 1;
    __syncthreads();
    if (threadIdx.x == 0) g_is64 = bad ? 0 : 1;
}
__global__ void cvt_edges_k(const void* __restrict__ ei) {
    int e = blockIdx.x * blockDim.x + threadIdx.x;
    if (e >= N_EDGES) return;
    if (g_is64) {
        const long long* p = (const long long*)ei;
        g_src[e] = (int)p[e];
        g_dst[e] = (int)p[e + N_EDGES];
    } else {
        const int* p = (const int*)ei;
        g_src[e] = p[e];
        g_dst[e] = p[e + N_EDGES];
    }
}

// ---------------- degree / norm / CSR build ----------------
__global__ void cnt_zero_k() {
    int i = blockIdx.x * blockDim.x + threadIdx.x;
    if (i < N_NODES) { g_cnt[i] = 0; g_fill[i] = 0; }
}
__global__ void deg_count_k() {
    int e = blockIdx.x * blockDim.x + threadIdx.x;
    if (e < N_EDGES) atomicAdd(&g_cnt[g_dst[e]], 1);
}
__global__ void dinv_k() {
    int i = blockIdx.x * blockDim.x + threadIdx.x;
    if (i < N_NODES) g_dinv[i] = rsqrtf((float)(g_cnt[i] + 1));
}
__global__ void scan1_k() {
    __shared__ int sh[SCAN_CHUNK];
    int i = blockIdx.x * SCAN_CHUNK + threadIdx.x;
    sh[threadIdx.x] = (i < N_NODES) ? g_cnt[i] : 0;
    __syncthreads();
    for (int off = SCAN_CHUNK / 2; off > 0; off >>= 1) {
        if (threadIdx.x < off) sh[threadIdx.x] += sh[threadIdx.x + off];
        __syncthreads();
    }
    if (threadIdx.x == 0) g_blocksums[blockIdx.x] = sh[0];
}
__global__ void scan2_k() {
    if (threadIdx.x == 0) {
        int run = 0;
        for (int b = 0; b < SCAN_NB; b++) {
            int v = g_blocksums[b];
            g_blocksums[b] = run;
            run += v;
        }
    }
}
__global__ void scan3_k() {
    __shared__ int sh[SCAN_CHUNK];
    int i = blockIdx.x * SCAN_CHUNK + threadIdx.x;
    int v = (i < N_NODES) ? g_cnt[i] : 0;
    sh[threadIdx.x] = v;
    __syncthreads();
    for (int off = 1; off < SCAN_CHUNK; off <<= 1) {
        int t = (threadIdx.x >= off) ? sh[threadIdx.x - off] : 0;
        __syncthreads();
        sh[threadIdx.x] += t;
        __syncthreads();
    }
    if (i < N_NODES)
        g_rowptr[i] = g_blocksums[blockIdx.x] + sh[threadIdx.x] - v;
}
__global__ void scatter_k() {
    int e = blockIdx.x * blockDim.x + threadIdx.x;
    if (e >= N_EDGES) return;
    int d = g_dst[e];
    int pos = g_rowptr[d] + atomicAdd(&g_fill[d], 1);
    g_csrc[pos] = g_src[e];
}

// ---------------- gather + split-bf16 epilogue: out row [hi(C)|lo(C)] ----------------
template <int C>
__global__ __launch_bounds__(256)
void gather_split_k(const float* __restrict__ xin, __nv_bfloat16* __restrict__ aout) {
    constexpr int V = C / 128;
    int d = (blockIdx.x * blockDim.x + threadIdx.x) >> 5;
    int lane = threadIdx.x & 31;
    if (d >= N_NODES) return;
    float dd = g_dinv[d];

    float4 acc[V];
    {
        float sl = dd * dd;
        const float4* self = reinterpret_cast<const float4*>(xin + (size_t)d * C);
#pragma unroll
        for (int v = 0; v < V; v++) {
            float4 t = self[lane + v * 32];
            acc[v].x = t.x * sl; acc[v].y = t.y * sl;
            acc[v].z = t.z * sl; acc[v].w = t.w * sl;
        }
    }
    int start = g_rowptr[d];
    int cnt = g_cnt[d];
    for (int j = 0; j < cnt; j++) {
        int s = g_csrc[start + j];
        float nrm = g_dinv[s] * dd;
        const float4* xr = reinterpret_cast<const float4*>(xin + (size_t)s * C);
#pragma unroll
        for (int v = 0; v < V; v++) {
            float4 t = xr[lane + v * 32];
            acc[v].x += t.x * nrm; acc[v].y += t.y * nrm;
            acc[v].z += t.z * nrm; acc[v].w += t.w * nrm;
        }
    }
    size_t base = (size_t)d * (2 * C);
#pragma unroll
    for (int v = 0; v < V; v++) {
        int col = (lane + v * 32) * 4;
        float vals[4] = {acc[v].x, acc[v].y, acc[v].z, acc[v].w};
        __nv_bfloat16 hi[4], lo[4];
#pragma unroll
        for (int t = 0; t < 4; t++) {
            hi[t] = __float2bfloat16(vals[t]);
            lo[t] = __float2bfloat16(vals[t] - __bfloat162float(hi[t]));
        }
        *reinterpret_cast<__nv_bfloat162*>(&aout[base + col])         = __halves2bfloat162(hi[0], hi[1]);
        *reinterpret_cast<__nv_bfloat162*>(&aout[base + col + 2])     = __halves2bfloat162(hi[2], hi[3]);
        *reinterpret_cast<__nv_bfloat162*>(&aout[base + C + col])     = __halves2bfloat162(lo[0], lo[1]);
        *reinterpret_cast<__nv_bfloat162*>(&aout[base + C + col + 2]) = __halves2bfloat162(lo[2], lo[3]);
    }
}

// ---------------- weight split + transpose: Wt[n] = [hi(K)|lo(K)] ----------------
__global__ void split_wt_k(const float* __restrict__ W, __nv_bfloat16* __restrict__ Wt,
                           int K, int Nn) {
    int idx = blockIdx.x * blockDim.x + threadIdx.x;
    if (idx >= K * Nn) return;
    int k = idx / Nn, n = idx % Nn;
    float v = W[idx];
    __nv_bfloat16 hi = __float2bfloat16(v);
    __nv_bfloat16 lo = __float2bfloat16(v - __bfloat162float(hi));
    size_t base = (size_t)n * (2 * K);
    Wt[base + k]     = hi;
    Wt[base + K + k] = lo;
}
__global__ void logits_init_k(const float* __restrict__ bd2) {
    size_t idx = (size_t)blockIdx.x * blockDim.x + threadIdx.x;
    if (idx < (size_t)N_NODES * 6)
        g_logits[idx] = bd2[idx % 6];
}

// ============ dedup split-bf16 GEMM, 256x256 block, 64x64 warp tile ============
// 512 threads = 16 warps (4m x 4n). 2-stage cp.async (R10-style: issue->wait->sync->compute->sync).
// Stage layout: [Ah(256xSROW) | Al | Bh(256xSROW) | Bl]
#define TA_B (256 * SROW * 2)   // 20480 bytes
#define TB_B (256 * SROW * 2)   // 20480 bytes
#define STAGE_B (2 * TA_B + 2 * TB_B)   // 81920
#define NSTAGE 2

template <bool DENSE_EPI>
__global__ __launch_bounds__(512)
void gemm_hilo_k(const __nv_bfloat16* __restrict__ A2,
                 const __nv_bfloat16* __restrict__ Wt,
                 float* __restrict__ Cout,
                 const float* __restrict__ bd1,
                 const float* __restrict__ Wd2,
                 int M, int Nn, int K) {
    extern __shared__ __nv_bfloat16 sm[];
    __shared__ float W2s[256][6];
    __shared__ float b1s[256];
    __shared__ float rowacc4[4][256][6];

    const int tid  = threadIdx.x;
    const int warp = tid >> 5, lane = tid & 31;
    const int g = lane >> 2, tig = lane & 3;
    const int wm = (warp >> 2) * 64, wn = (warp & 3) * 64;
    const int lmat = lane >> 3, lrow = lane & 7;
    // A-operand ldsm lane address
    const int rowSelA = (lmat & 1) * 8 + lrow;
    const int koffA   = (lane >> 4) * 8;
    // B-operand ldsm lane address
    const int rowSelB = (lane >> 4) * 8 + lrow;
    const int koffB   = (lmat & 1) * 8;
    const int rowBase = blockIdx.y * 256;
    const int n0 = blockIdx.x * 256;

    if (DENSE_EPI) {
        for (int i = tid; i < 1536; i += 512)
            W2s[i / 6][i % 6] = Wd2[(size_t)(n0 + i / 6) * 6 + (i % 6)];
        if (tid < 256) b1s[tid] = bd1[n0 + tid];
    }

    uint32_t smBase = (uint32_t)__cvta_generic_to_shared(sm);
    const int nIter = K / 32;

    // stage loader: 8 x 16B chunks per thread (A: 2048 chunks, B: 2048)
    auto issue = [&](int it) {
        uint32_t sb = smBase + (uint32_t)(it & 1) * STAGE_B;
        int k0 = it * 32;
#pragma unroll
        for (int t = 0; t < 8; t++) {
            int ci = tid + t * 512;
            if (ci < 2048) {
                int tileA = ci >> 10;
                int local = ci & 1023;
                int row = local >> 2;
                int ch = (local & 3) * 8;
                int gr = rowBase + row;
                int ok = (gr < M) ? 16 : 0;
                const __nv_bfloat16* src =
                    A2 + (size_t)(ok ? gr : 0) * (2 * K) + tileA * K + k0 + ch;
                uint32_t dst = sb + (uint32_t)(tileA * TA_B + (row * SROW + ch) * 2);
                cpa16(dst, src, ok);
            } else {
                int bi = ci - 2048;
                int tileB = bi >> 10;
                int local = bi & 1023;
                int row = local >> 2;
                int ch = (local & 3) * 8;
                const __nv_bfloat16* src =
                    Wt + (size_t)(n0 + row) * (2 * K) + tileB * K + k0 + ch;
                uint32_t dst = sb + (uint32_t)(2 * TA_B + tileB * TB_B + (row * SROW + ch) * 2);
                cpa16(dst, src, 16);
            }
        }
        cpa_commit();
    };

    issue(0);

    float acc[4][8][4];
#pragma unroll
    for (int s = 0; s < 4; s++)
#pragma unroll
        for (int j = 0; j < 8; j++)
#pragma unroll
            for (int c = 0; c < 4; c++) acc[s][j][c] = 0.f;

    for (int it = 0; it < nIter; it++) {
        if (it + 1 < nIter) { issue(it + 1); cpa_wait<1>(); }
        else cpa_wait<0>();
        __syncthreads();

        uint32_t base = smBase + (uint32_t)(it & 1) * STAGE_B;
        uint32_t bAh = base;
        uint32_t bAl = base + TA_B;
        uint32_t bBh = base + 2 * TA_B;
        uint32_t bBl = bBh + TB_B;
#pragma unroll
        for (int kk = 0; kk < 32; kk += 16) {
            uint32_t ah[4][4], al[4][4], bh[8][2], bl[8][2];
#pragma unroll
            for (int s = 0; s < 4; s++) {
                uint32_t offA = (uint32_t)(((wm + s * 16 + rowSelA) * SROW + koffA + kk) * 2);
                ldsm_x4(ah[s][0], ah[s][1], ah[s][2], ah[s][3], bAh + offA);
                ldsm_x4(al[s][0], al[s][1], al[s][2], al[s][3], bAl + offA);
            }
#pragma unroll
            for (int p = 0; p < 4; p++) {
                uint32_t offB = (uint32_t)(((wn + p * 16 + rowSelB) * SROW + koffB + kk) * 2);
                ldsm_x4(bh[2 * p][0], bh[2 * p][1], bh[2 * p + 1][0], bh[2 * p + 1][1], bBh + offB);
                ldsm_x4(bl[2 * p][0], bl[2 * p][1], bl[2 * p + 1][0], bl[2 * p + 1][1], bBl + offB);
            }
#define MMA(A_, B_) \
    asm volatile("mma.sync.aligned.m16n8k16.row.col.f32.bf16.bf16.f32 " \
                 "{%0,%1,%2,%3}, {%4,%5,%6,%7}, {%8,%9}, {%0,%1,%2,%3};" \
                 : "+f"(acc[s][j][0]), "+f"(acc[s][j][1]), \
                   "+f"(acc[s][j][2]), "+f"(acc[s][j][3]) \
                 : "r"(A_[s][0]), "r"(A_[s][1]), "r"(A_[s][2]), "r"(A_[s][3]), \
                   "r"(B_[j][0]), "r"(B_[j][1]))
#pragma unroll
            for (int s = 0; s < 4; s++)
#pragma unroll
                for (int j = 0; j < 8; j++) {
                    MMA(ah, bh);
                    MMA(ah, bl);
                    MMA(al, bh);
                }
#undef MMA
        }
        __syncthreads();
    }

    if (!DENSE_EPI) {
#pragma unroll
        for (int s = 0; s < 4; s++) {
            int r0 = rowBase + wm + s * 16 + g;
            int r1 = r0 + 8;
#pragma unroll
            for (int j = 0; j < 8; j++) {
                int col = n0 + wn + j * 8 + 2 * tig;
                if (r0 < M) {
                    Cout[(size_t)r0 * Nn + col]     = acc[s][j][0];
                    Cout[(size_t)r0 * Nn + col + 1] = acc[s][j][1];
                }
                if (r1 < M) {
                    Cout[(size_t)r1 * Nn + col]     = acc[s][j][2];
                    Cout[(size_t)r1 * Nn + col + 1] = acc[s][j][3];
                }
            }
        }
    } else {
        float acc6[8][6];
#pragma unroll
        for (int r = 0; r < 8; r++)
#pragma unroll
            for (int c = 0; c < 6; c++) acc6[r][c] = 0.f;
#pragma unroll
        for (int s = 0; s < 4; s++)
#pragma unroll
            for (int j = 0; j < 8; j++) {
                int col = wn + j * 8 + 2 * tig;
                float b0 = b1s[col], b1 = b1s[col + 1];
                float t;
                t = acc[s][j][0] + b0; t = t >= 0.f ? t : SLOPE * t;
#pragma unroll
                for (int c = 0; c < 6; c++) acc6[s * 2 + 0][c] += t * W2s[col][c];
                t = acc[s][j][1] + b1; t = t >= 0.f ? t : SLOPE * t;
#pragma unroll
                for (int c = 0; c < 6; c++) acc6[s * 2 + 0][c] += t * W2s[col + 1][c];
                t = acc[s][j][2] + b0; t = t >= 0.f ? t : SLOPE * t;
#pragma unroll
                for (int c = 0; c < 6; c++) acc6[s * 2 + 1][c] += t * W2s[col][c];
                t = acc[s][j][3] + b1; t = t >= 0.f ? t : SLOPE * t;
#pragma unroll
                for (int c = 0; c < 6; c++) acc6[s * 2 + 1][c] += t * W2s[col + 1][c];
            }
        // reduce over the 4 tig lanes per row, write private n-warp slice
#pragma unroll
        for (int r = 0; r < 8; r++)
#pragma unroll
            for (int c = 0; c < 6; c++) {
                float v = acc6[r][c];
                v += __shfl_xor_sync(0xffffffffu, v, 1);
                v += __shfl_xor_sync(0xffffffffu, v, 2);
                acc6[r][c] = v;
            }
        if (tig == 0) {
            int nw = warp & 3;
#pragma unroll
            for (int s = 0; s < 4; s++) {
                int r0 = wm + s * 16 + g;
                int r1 = r0 + 8;
#pragma unroll
                for (int c = 0; c < 6; c++) {
                    rowacc4[nw][r0][c] = acc6[s * 2 + 0][c];
                    rowacc4[nw][r1][c] = acc6[s * 2 + 1][c];
                }
            }
        }
        __syncthreads();
        for (int i = tid; i < 1536; i += 512) {
            int r = i / 6, c = i % 6;
            float v = rowacc4[0][r][c] + rowacc4[1][r][c] + rowacc4[2][r][c] + rowacc4[3][r][c];
            if (rowBase + r < M)
                atomicAdd(&Cout[(size_t)(rowBase + r) * 6 + c], v);
        }
    }
}

// ---------------- BatchNorm ----------------
__global__ void bn_zero_k(int C) {
    int c = threadIdx.x + blockIdx.x * blockDim.x;
    if (c < C) { g_colsum[c] = 0.f; g_colsq[c] = 0.f; }
}
template <int C>
__global__ void bn_reduce_k(const float* __restrict__ h) {
    int c = threadIdx.x;
    int rows_per = (N_NODES + gridDim.x - 1) / gridDim.x;
    int r0 = blockIdx.x * rows_per;
    int r1 = min(r0 + rows_per, N_NODES);
    float s = 0.f, sq = 0.f;
    for (int r = r0; r < r1; r++) {
        float v = h[(size_t)r * C + c];
        s += v; sq += v * v;
    }
    atomicAdd(&g_colsum[c], s);
    atomicAdd(&g_colsq[c], sq);
}
__global__ void bn_scale_k(const float* __restrict__ g, const float* __restrict__ be, int C) {
    int c = threadIdx.x + blockIdx.x * blockDim.x;
    if (c < C) {
        float mean = g_colsum[c] * (1.0f / N_NODES);
        float var  = g_colsq[c] * (1.0f / N_NODES) - mean * mean;
        float a = g[c] * rsqrtf(var + BN_EPS);
        g_scale[c] = a;
        g_shift[c] = be[c] - mean * a;
    }
}
template <int C>
__global__ void bn_apply_k(float* __restrict__ h) {
    size_t idx = (size_t)blockIdx.x * blockDim.x + threadIdx.x;
    if (idx < (size_t)N_NODES * C) {
        int c = (int)(idx & (C - 1));
        float v = h[idx] * g_scale[c] + g_shift[c];
        h[idx] = v >= 0.f ? v : SLOPE * v;
    }
}

// ---------------- fused BN-apply + leaky + split: [hi(512)|lo(512)] ----------------
__global__ void split_a_fused_k(const float* __restrict__ h2raw, __nv_bfloat16* __restrict__ a2) {
    size_t idx = (size_t)blockIdx.x * blockDim.x + threadIdx.x;
    if (idx >= (size_t)N_NODES * 512) return;
    int m = (int)(idx >> 9), k = (int)(idx & 511);
    float v = h2raw[idx] * g_scale[k] + g_shift[k];
    v = v >= 0.f ? v : SLOPE * v;
    __nv_bfloat16 hi = __float2bfloat16(v);
    __nv_bfloat16 lo = __float2bfloat16(v - __bfloat162float(hi));
    size_t base = (size_t)m * 1024;
    a2[base + k]       = hi;
    a2[base + 512 + k] = lo;
}

// ---------------- softmax ----------------
__global__ void softmax_k(const float* __restrict__ logits, float* __restrict__ out) {
    int r = blockIdx.x * blockDim.x + threadIdx.x;
    if (r >= N_NODES) return;
    float v[6];
    float m = -1e30f;
#pragma unroll
    for (int j = 0; j < 6; j++) { v[j] = logits[(size_t)r * 6 + j]; m = fmaxf(m, v[j]); }
    float ssum = 0.f;
#pragma unroll
    for (int j = 0; j < 6; j++) { v[j] = __expf(v[j] - m); ssum += v[j]; }
    float inv = 1.0f / ssum;
#pragma unroll
    for (int j = 0; j < 6; j++) out[(size_t)r * 6 + j] = v[j] * inv;
}

// ---------------- launch ----------------
static inline void* symp(const void* s) {
    void* p = nullptr;
    cudaGetSymbolAddress(&p, s);
    return p;
}

extern "C" void kernel_launch(void* const* d_in, const int* in_sizes, int n_in,
                              void* d_out, int out_size) {
    const float* x    = (const float*)d_in[0];
    const void*  ei   = d_in[1];
    const float* W1   = (const float*)d_in[2];
    const float* W2   = (const float*)d_in[4];
    const float* g1   = (const float*)d_in[6];
    const float* be1  = (const float*)d_in[7];
    const float* g2   = (const float*)d_in[8];
    const float* be2  = (const float*)d_in[9];
    const float* Wd1  = (const float*)d_in[10];
    const float* bd1  = (const float*)d_in[11];
    const float* Wd2  = (const float*)d_in[12];
    const float* bd2  = (const float*)d_in[13];
    float*       out  = (float*)d_out;

    unsigned char* arena = (unsigned char*)symp(g_arena);
    __nv_bfloat16* ga1 = (__nv_bfloat16*)arena;
    __nv_bfloat16* ga2 = (__nv_bfloat16*)(arena + (size_t)N_NODES * 256 * 2);
    __nv_bfloat16* a2  = (__nv_bfloat16*)arena;
    float* h1  = (float*)symp(g_h1);
    float* h2  = (float*)symp(g_h2);
    float* lg  = (float*)symp(g_logits);
    __nv_bfloat16* wd  = (__nv_bfloat16*)symp(g_wd);
    __nv_bfloat16* w1s = (__nv_bfloat16*)symp(g_w1s);
    __nv_bfloat16* w2s = (__nv_bfloat16*)symp(g_w2s);

    const int smemBytes = STAGE_B * NSTAGE;   // 163840
    cudaFuncSetAttribute(gemm_hilo_k<false>, cudaFuncAttributeMaxDynamicSharedMemorySize, smemBytes);
    cudaFuncSetAttribute(gemm_hilo_k<true>,  cudaFuncAttributeMaxDynamicSharedMemorySize, smemBytes);

    // edge conversion + CSR build
    detect_k<<<1, 256>>>((const unsigned long long*)ei);
    cvt_edges_k<<<(N_EDGES + 255) / 256, 256>>>(ei);
    cnt_zero_k<<<(N_NODES + 255) / 256, 256>>>();
    deg_count_k<<<(N_EDGES + 255) / 256, 256>>>();
    dinv_k<<<(N_NODES + 255) / 256, 256>>>();
    scan1_k<<<SCAN_NB, SCAN_CHUNK>>>();
    scan2_k<<<1, 32>>>();
    scan3_k<<<SCAN_NB, SCAN_CHUNK>>>();
    scatter_k<<<(N_EDGES + 255) / 256, 256>>>();

    // weight prep
    split_wt_k<<<(int)(((size_t)512 * 4096 + 255) / 256), 256>>>(Wd1, wd, 512, 4096);
    split_wt_k<<<(128 * 256 + 255) / 256, 256>>>(W1, w1s, 128, 256);
    split_wt_k<<<(256 * 512 + 255) / 256, 256>>>(W2, w2s, 256, 512);
    logits_init_k<<<(N_NODES * 6 + 255) / 256, 256>>>(bd2);

    // ---- layer 1 ----
    gather_split_k<128><<<(int)(((size_t)N_NODES * 32 + 255) / 256), 256>>>(x, ga1);
    {
        dim3 grid(256 / 256, (N_NODES + 255) / 256);
        gemm_hilo_k<false><<<grid, 512, smemBytes>>>(ga1, w1s, h1, nullptr, nullptr, N_NODES, 256, 128);
    }
    bn_zero_k<<<2, 256>>>(256);
    bn_reduce_k<256><<<512, 256>>>(h1);
    bn_scale_k<<<1, 256>>>(g1, be1, 256);
    bn_apply_k<256><<<(int)(((size_t)N_NODES * 256 + 255) / 256), 256>>>(h1);

    // ---- layer 2 ----
    gather_split_k<256><<<(int)(((size_t)N_NODES * 32 + 255) / 256), 256>>>(h1, ga2);
    {
        dim3 grid(512 / 256, (N_NODES + 255) / 256);
        gemm_hilo_k<false><<<grid, 512, smemBytes>>>(ga2, w2s, h2, nullptr, nullptr, N_NODES, 512, 256);
    }
    bn_zero_k<<<2, 256>>>(512);
    bn_reduce_k<512><<<512, 512>>>(h2);
    bn_scale_k<<<2, 256>>>(g2, be2, 512);

    // ---- fused BN-apply + leaky + split ----
    split_a_fused_k<<<(int)(((size_t)N_NODES * 512 + 255) / 256), 256>>>(h2, a2);

    // ---- dense1 + LeakyReLU + dense2 partials ----
    {
        dim3 grid(4096 / 256, (N_NODES + 255) / 256);
        gemm_hilo_k<true><<<grid, 512, smemBytes>>>(a2, wd, lg, bd1, Wd2, N_NODES, 4096, 512);
    }

    // ---- softmax ----
    softmax_k<<<(N_NODES + 255) / 256, 256>>>(lg, out);
}

// round 17
// speedup vs baseline: 1.5051x; 1.5051x over previous
#include <cuda_runtime.h>
#include <cuda_bf16.h>
#include <cstdint>

#define N_NODES 100000
#define N_EDGES 3200000
#define BN_EPS 1e-5f
#define SLOPE 0.01f
#define SCAN_CHUNK 512
#define SCAN_NB ((N_NODES + SCAN_CHUNK - 1) / SCAN_CHUNK)
#define SROW 40   // smem row stride (bf16): 80B, 16B-aligned, ldsm conflict-free (validated R12/R15)

// ---------------- scratch (static device globals; no allocation) ----------------
__device__ unsigned char g_arena[(size_t)N_NODES * 1024 * 2];  // 204.8 MB
__device__ float g_dinv[N_NODES];
__device__ int   g_cnt [N_NODES];
__device__ int   g_fill[N_NODES];
__device__ int   g_rowptr[N_NODES];
__device__ int   g_blocksums[SCAN_NB];
__device__ int   g_src[N_EDGES];
__device__ int   g_dst[N_EDGES];
__device__ int   g_csrc[N_EDGES];
__device__ int   g_is64;
__device__ float g_h1 [(size_t)N_NODES * 256];
__device__ float g_h2 [(size_t)N_NODES * 512];
__device__ __nv_bfloat16 g_wd [(size_t)4096 * 1024];
__device__ __nv_bfloat16 g_w1s[(size_t)256 * 256];
__device__ __nv_bfloat16 g_w2s[(size_t)512 * 512];
__device__ float g_logits[(size_t)N_NODES * 6];
__device__ float g_colsum[512];
__device__ float g_colsq [512];
__device__ float g_scale [512];
__device__ float g_shift [512];

// ---------------- cp.async / ldmatrix helpers ----------------
__device__ __forceinline__ void cpa16(uint32_t dst, const void* src, int srcsize) {
    asm volatile("cp.async.cg.shared.global [%0], [%1], 16, %2;"
                 :: "r"(dst), "l"(src), "r"(srcsize));
}
__device__ __forceinline__ void cpa_commit() { asm volatile("cp.async.commit_group;"); }
template <int N>
__device__ __forceinline__ void cpa_wait() { asm volatile("cp.async.wait_group %0;" :: "n"(N)); }
__device__ __forceinline__ void ldsm_x4(uint32_t& r0, uint32_t& r1, uint32_t& r2, uint32_t& r3,
                                        uint32_t addr) {
    asm volatile("ldmatrix.sync.aligned.m8n8.x4.shared.b16 {%0,%1,%2,%3}, [%4];"
                 : "=r"(r0), "=r"(r1), "=r"(r2), "=r"(r3) : "r"(addr));
}

// ---------------- edge dtype detection + conversion ----------------
__global__ void detect_k(const unsigned long long* __restrict__ p) {
    __shared__ int bad;
    if (threadIdx.x == 0) bad = 0;
    __syncthreads();
    for (int i = threadIdx.x; i < 4096; i += 256)
        if (p[i] >= (unsigned long long)N_NODES) bad = 1;
    __syncthreads();
    if (threadIdx.x == 0) g_is64 = bad ? 0 : 1;
}
__global__ void cvt_edges_k(const void* __restrict__ ei) {
    int e = blockIdx.x * blockDim.x + threadIdx.x;
    if (e >= N_EDGES) return;
    if (g_is64) {
        const long long* p = (const long long*)ei;
        g_src[e] = (int)p[e];
        g_dst[e] = (int)p[e + N_EDGES];
    } else {
        const int* p = (const int*)ei;
        g_src[e] = p[e];
        g_dst[e] = p[e + N_EDGES];
    }
}

// ---------------- degree / norm / CSR build ----------------
__global__ void cnt_zero_k() {
    int i = blockIdx.x * blockDim.x + threadIdx.x;
    if (i < N_NODES) { g_cnt[i] = 0; g_fill[i] = 0; }
}
__global__ void deg_count_k() {
    int e = blockIdx.x * blockDim.x + threadIdx.x;
    if (e < N_EDGES) atomicAdd(&g_cnt[g_dst[e]], 1);
}
__global__ void dinv_k() {
    int i = blockIdx.x * blockDim.x + threadIdx.x;
    if (i < N_NODES) g_dinv[i] = rsqrtf((float)(g_cnt[i] + 1));
}
__global__ void scan1_k() {
    __shared__ int sh[SCAN_CHUNK];
    int i = blockIdx.x * SCAN_CHUNK + threadIdx.x;
    sh[threadIdx.x] = (i < N_NODES) ? g_cnt[i] : 0;
    __syncthreads();
    for (int off = SCAN_CHUNK / 2; off > 0; off >>= 1) {
        if (threadIdx.x < off) sh[threadIdx.x] += sh[threadIdx.x + off];
        __syncthreads();
    }
    if (threadIdx.x == 0) g_blocksums[blockIdx.x] = sh[0];
}
__global__ void scan2_k() {
    if (threadIdx.x == 0) {
        int run = 0;
        for (int b = 0; b < SCAN_NB; b++) {
            int v = g_blocksums[b];
            g_blocksums[b] = run;
            run += v;
        }
    }
}
__global__ void scan3_k() {
    __shared__ int sh[SCAN_CHUNK];
    int i = blockIdx.x * SCAN_CHUNK + threadIdx.x;
    int v = (i < N_NODES) ? g_cnt[i] : 0;
    sh[threadIdx.x] = v;
    __syncthreads();
    for (int off = 1; off < SCAN_CHUNK; off <<= 1) {
        int t = (threadIdx.x >= off) ? sh[threadIdx.x - off] : 0;
        __syncthreads();
        sh[threadIdx.x] += t;
        __syncthreads();
    }
    if (i < N_NODES)
        g_rowptr[i] = g_blocksums[blockIdx.x] + sh[threadIdx.x] - v;
}
__global__ void scatter_k() {
    int e = blockIdx.x * blockDim.x + threadIdx.x;
    if (e >= N_EDGES) return;
    int d = g_dst[e];
    int pos = g_rowptr[d] + atomicAdd(&g_fill[d], 1);
    g_csrc[pos] = g_src[e];
}

// ---------------- gather + split-bf16 epilogue: out row [hi(C)|lo(C)] ----------------
template <int C>
__global__ __launch_bounds__(256)
void gather_split_k(const float* __restrict__ xin, __nv_bfloat16* __restrict__ aout) {
    constexpr int V = C / 128;
    int d = (blockIdx.x * blockDim.x + threadIdx.x) >> 5;
    int lane = threadIdx.x & 31;
    if (d >= N_NODES) return;
    float dd = g_dinv[d];

    float4 acc[V];
    {
        float sl = dd * dd;
        const float4* self = reinterpret_cast<const float4*>(xin + (size_t)d * C);
#pragma unroll
        for (int v = 0; v < V; v++) {
            float4 t = self[lane + v * 32];
            acc[v].x = t.x * sl; acc[v].y = t.y * sl;
            acc[v].z = t.z * sl; acc[v].w = t.w * sl;
        }
    }
    int start = g_rowptr[d];
    int cnt = g_cnt[d];
    for (int j = 0; j < cnt; j++) {
        int s = g_csrc[start + j];
        float nrm = g_dinv[s] * dd;
        const float4* xr = reinterpret_cast<const float4*>(xin + (size_t)s * C);
#pragma unroll
        for (int v = 0; v < V; v++) {
            float4 t = xr[lane + v * 32];
            acc[v].x += t.x * nrm; acc[v].y += t.y * nrm;
            acc[v].z += t.z * nrm; acc[v].w += t.w * nrm;
        }
    }
    size_t base = (size_t)d * (2 * C);
#pragma unroll
    for (int v = 0; v < V; v++) {
        int col = (lane + v * 32) * 4;
        float vals[4] = {acc[v].x, acc[v].y, acc[v].z, acc[v].w};
        __nv_bfloat16 hi[4], lo[4];
#pragma unroll
        for (int t = 0; t < 4; t++) {
            hi[t] = __float2bfloat16(vals[t]);
            lo[t] = __float2bfloat16(vals[t] - __bfloat162float(hi[t]));
        }
        *reinterpret_cast<__nv_bfloat162*>(&aout[base + col])         = __halves2bfloat162(hi[0], hi[1]);
        *reinterpret_cast<__nv_bfloat162*>(&aout[base + col + 2])     = __halves2bfloat162(hi[2], hi[3]);
        *reinterpret_cast<__nv_bfloat162*>(&aout[base + C + col])     = __halves2bfloat162(lo[0], lo[1]);
        *reinterpret_cast<__nv_bfloat162*>(&aout[base + C + col + 2]) = __halves2bfloat162(lo[2], lo[3]);
    }
}

// ---------------- weight split + transpose: Wt[n] = [hi(K)|lo(K)] ----------------
__global__ void split_wt_k(const float* __restrict__ W, __nv_bfloat16* __restrict__ Wt,
                           int K, int Nn) {
    int idx = blockIdx.x * blockDim.x + threadIdx.x;
    if (idx >= K * Nn) return;
    int k = idx / Nn, n = idx % Nn;
    float v = W[idx];
    __nv_bfloat16 hi = __float2bfloat16(v);
    __nv_bfloat16 lo = __float2bfloat16(v - __bfloat162float(hi));
    size_t base = (size_t)n * (2 * K);
    Wt[base + k]     = hi;
    Wt[base + K + k] = lo;
}
__global__ void logits_init_k(const float* __restrict__ bd2) {
    size_t idx = (size_t)blockIdx.x * blockDim.x + threadIdx.x;
    if (idx < (size_t)N_NODES * 6)
        g_logits[idx] = bd2[idx % 6];
}

// ============ dedup split-bf16 GEMM, 128x256 block, 64x64 warp tile ============
// 256 threads = 8 warps (2m x 4n). 3-stage cp.async. Stage layout:
// [Ah(128xSROW) | Al | Bh(256xSROW) | Bl]
#define TA_B (128 * SROW * 2)   // A tile bytes (10240)
#define TB_B (256 * SROW * 2)   // B tile bytes (20480)
#define STAGE_B (2 * TA_B + 2 * TB_B)   // 61440
#define NSTAGE 3

template <bool DENSE_EPI>
__global__ __launch_bounds__(256)
void gemm_hilo_k(const __nv_bfloat16* __restrict__ A2,
                 const __nv_bfloat16* __restrict__ Wt,
                 float* __restrict__ Cout,
                 const float* __restrict__ bd1,
                 const float* __restrict__ Wd2,
                 int M, int Nn, int K) {
    extern __shared__ __nv_bfloat16 sm[];
    __shared__ float W2s[256][6];
    __shared__ float b1s[256];
    __shared__ float rowacc4[4][128][6];

    const int tid  = threadIdx.x;
    const int warp = tid >> 5, lane = tid & 31;
    const int g = lane >> 2, tig = lane & 3;
    const int wm = (warp >> 2) * 64, wn = (warp & 3) * 64;
    const int lmat = lane >> 3, lrow = lane & 7;
    // A-operand ldsm lane address (matrix order: r0-7/k0-7, r8-15/k0-7, r0-7/k8-15, r8-15/k8-15)
    const int rowSelA = (lmat & 1) * 8 + lrow;
    const int koffA   = (lane >> 4) * 8;
    // B-operand ldsm lane address (matrix order: n0-7/k0-7, n0-7/k8-15, n8-15/k0-7, n8-15/k8-15)
    const int rowSelB = (lane >> 4) * 8 + lrow;
    const int koffB   = (lmat & 1) * 8;
    const int rowBase = blockIdx.y * 128;
    const int n0 = blockIdx.x * 256;

    if (DENSE_EPI) {
        for (int i = tid; i < 1536; i += 256)
            W2s[i / 6][i % 6] = Wd2[(size_t)(n0 + i / 6) * 6 + (i % 6)];
        b1s[tid] = bd1[n0 + tid];
    }

    uint32_t smBase = (uint32_t)__cvta_generic_to_shared(sm);
    const int nIter = K / 32;

    // stage loader: 12 x 16B chunks per thread (A: 1024 chunks, B: 2048)
    auto issue = [&](int it) {
        uint32_t sb = smBase + (uint32_t)(it % NSTAGE) * STAGE_B;
        int k0 = it * 32;
#pragma unroll
        for (int t = 0; t < 12; t++) {
            int ci = tid + t * 256;
            if (ci < 1024) {
                int tileA = ci >> 9;
                int local = ci & 511;
                int row = local >> 2;
                int ch = (local & 3) * 8;
                int gr = rowBase + row;
                int ok = (gr < M) ? 16 : 0;
                const __nv_bfloat16* src =
                    A2 + (size_t)(ok ? gr : 0) * (2 * K) + tileA * K + k0 + ch;
                uint32_t dst = sb + (uint32_t)(tileA * TA_B + (row * SROW + ch) * 2);
                cpa16(dst, src, ok);
            } else {
                int bi = ci - 1024;
                int tileB = bi >> 10;
                int local = bi & 1023;
                int row = local >> 2;
                int ch = (local & 3) * 8;
                const __nv_bfloat16* src =
                    Wt + (size_t)(n0 + row) * (2 * K) + tileB * K + k0 + ch;
                uint32_t dst = sb + (uint32_t)(2 * TA_B + tileB * TB_B + (row * SROW + ch) * 2);
                cpa16(dst, src, 16);
            }
        }
        cpa_commit();
    };

    issue(0);
    if (nIter > 1) issue(1);

    float acc[4][8][4];
#pragma unroll
    for (int s = 0; s < 4; s++)
#pragma unroll
        for (int j = 0; j < 8; j++)
#pragma unroll
            for (int c = 0; c < 4; c++) acc[s][j][c] = 0.f;

    for (int it = 0; it < nIter; it++) {
        if (it + 1 < nIter) cpa_wait<1>(); else cpa_wait<0>();
        __syncthreads();
        if (it + 2 < nIter) issue(it + 2);

        uint32_t base = smBase + (uint32_t)(it % NSTAGE) * STAGE_B;
        uint32_t bAh = base;
        uint32_t bAl = base + TA_B;
        uint32_t bBh = base + 2 * TA_B;
        uint32_t bBl = bBh + TB_B;
#pragma unroll
        for (int kk = 0; kk < 32; kk += 16) {
            uint32_t ah[4][4], al[4][4], bh[8][2], bl[8][2];
#pragma unroll
            for (int s = 0; s < 4; s++) {
                uint32_t offA = (uint32_t)(((wm + s * 16 + rowSelA) * SROW + koffA + kk) * 2);
                ldsm_x4(ah[s][0], ah[s][1], ah[s][2], ah[s][3], bAh + offA);
                ldsm_x4(al[s][0], al[s][1], al[s][2], al[s][3], bAl + offA);
            }
#pragma unroll
            for (int p = 0; p < 4; p++) {
                uint32_t offB = (uint32_t)(((wn + p * 16 + rowSelB) * SROW + koffB + kk) * 2);
                ldsm_x4(bh[2 * p][0], bh[2 * p][1], bh[2 * p + 1][0], bh[2 * p + 1][1], bBh + offB);
                ldsm_x4(bl[2 * p][0], bl[2 * p][1], bl[2 * p + 1][0], bl[2 * p + 1][1], bBl + offB);
            }
#define MMA(A_, B_) \
    asm volatile("mma.sync.aligned.m16n8k16.row.col.f32.bf16.bf16.f32 " \
                 "{%0,%1,%2,%3}, {%4,%5,%6,%7}, {%8,%9}, {%0,%1,%2,%3};" \
                 : "+f"(acc[s][j][0]), "+f"(acc[s][j][1]), \
                   "+f"(acc[s][j][2]), "+f"(acc[s][j][3]) \
                 : "r"(A_[s][0]), "r"(A_[s][1]), "r"(A_[s][2]), "r"(A_[s][3]), \
                   "r"(B_[j][0]), "r"(B_[j][1]))
#pragma unroll
            for (int s = 0; s < 4; s++)
#pragma unroll
                for (int j = 0; j < 8; j++) {
                    MMA(ah, bh);
                    MMA(ah, bl);
                    MMA(al, bh);
                }
#undef MMA
        }
    }
    __syncthreads();

    if (!DENSE_EPI) {
#pragma unroll
        for (int s = 0; s < 4; s++) {
            int r0 = rowBase + wm + s * 16 + g;
            int r1 = r0 + 8;
#pragma unroll
            for (int j = 0; j < 8; j++) {
                int col = n0 + wn + j * 8 + 2 * tig;
                if (r0 < M) {
                    Cout[(size_t)r0 * Nn + col]     = acc[s][j][0];
                    Cout[(size_t)r0 * Nn + col + 1] = acc[s][j][1];
                }
                if (r1 < M) {
                    Cout[(size_t)r1 * Nn + col]     = acc[s][j][2];
                    Cout[(size_t)r1 * Nn + col + 1] = acc[s][j][3];
                }
            }
        }
    } else {
        float acc6[8][6];
#pragma unroll
        for (int r = 0; r < 8; r++)
#pragma unroll
            for (int c = 0; c < 6; c++) acc6[r][c] = 0.f;
#pragma unroll
        for (int s = 0; s < 4; s++)
#pragma unroll
            for (int j = 0; j < 8; j++) {
                int col = wn + j * 8 + 2 * tig;
                float b0 = b1s[col], b1 = b1s[col + 1];
                float t;
                t = acc[s][j][0] + b0; t = t >= 0.f ? t : SLOPE * t;
#pragma unroll
                for (int c = 0; c < 6; c++) acc6[s * 2 + 0][c] += t * W2s[col][c];
                t = acc[s][j][1] + b1; t = t >= 0.f ? t : SLOPE * t;
#pragma unroll
                for (int c = 0; c < 6; c++) acc6[s * 2 + 0][c] += t * W2s[col + 1][c];
                t = acc[s][j][2] + b0; t = t >= 0.f ? t : SLOPE * t;
#pragma unroll
                for (int c = 0; c < 6; c++) acc6[s * 2 + 1][c] += t * W2s[col][c];
                t = acc[s][j][3] + b1; t = t >= 0.f ? t : SLOPE * t;
#pragma unroll
                for (int c = 0; c < 6; c++) acc6[s * 2 + 1][c] += t * W2s[col + 1][c];
            }
        // reduce over the 4 tig lanes per row, write private n-warp slice
#pragma unroll
        for (int r = 0; r < 8; r++)
#pragma unroll
            for (int c = 0; c < 6; c++) {
                float v = acc6[r][c];
                v += __shfl_xor_sync(0xffffffffu, v, 1);
                v += __shfl_xor_sync(0xffffffffu, v, 2);
                acc6[r][c] = v;
            }
        if (tig == 0) {
            int nw = warp & 3;
#pragma unroll
            for (int s = 0; s < 4; s++) {
                int r0 = wm + s * 16 + g;
                int r1 = r0 + 8;
#pragma unroll
                for (int c = 0; c < 6; c++) {
                    rowacc4[nw][r0][c] = acc6[s * 2 + 0][c];
                    rowacc4[nw][r1][c] = acc6[s * 2 + 1][c];
                }
            }
        }
        __syncthreads();
        for (int i = tid; i < 768; i += 256) {
            int r = i / 6, c = i % 6;
            float v = rowacc4[0][r][c] + rowacc4[1][r][c] + rowacc4[2][r][c] + rowacc4[3][r][c];
            if (rowBase + r < M)
                atomicAdd(&Cout[(size_t)(rowBase + r) * 6 + c], v);
        }
    }
}

// ---------------- BatchNorm ----------------
__global__ void bn_zero_k(int C) {
    int c = threadIdx.x + blockIdx.x * blockDim.x;
    if (c < C) { g_colsum[c] = 0.f; g_colsq[c] = 0.f; }
}
template <int C>
__global__ void bn_reduce_k(const float* __restrict__ h) {
    int c = threadIdx.x;
    int rows_per = (N_NODES + gridDim.x - 1) / gridDim.x;
    int r0 = blockIdx.x * rows_per;
    int r1 = min(r0 + rows_per, N_NODES);
    float s = 0.f, sq = 0.f;
    for (int r = r0; r < r1; r++) {
        float v = h[(size_t)r * C + c];
        s += v; sq += v * v;
    }
    atomicAdd(&g_colsum[c], s);
    atomicAdd(&g_colsq[c], sq);
}
__global__ void bn_scale_k(const float* __restrict__ g, const float* __restrict__ be, int C) {
    int c = threadIdx.x + blockIdx.x * blockDim.x;
    if (c < C) {
        float mean = g_colsum[c] * (1.0f / N_NODES);
        float var  = g_colsq[c] * (1.0f / N_NODES) - mean * mean;
        float a = g[c] * rsqrtf(var + BN_EPS);
        g_scale[c] = a;
        g_shift[c] = be[c] - mean * a;
    }
}
template <int C>
__global__ void bn_apply_k(float* __restrict__ h) {
    size_t idx = (size_t)blockIdx.x * blockDim.x + threadIdx.x;
    if (idx < (size_t)N_NODES * C) {
        int c = (int)(idx & (C - 1));
        float v = h[idx] * g_scale[c] + g_shift[c];
        h[idx] = v >= 0.f ? v : SLOPE * v;
    }
}

// ---------------- fused BN-apply + leaky + split: [hi(512)|lo(512)] ----------------
__global__ void split_a_fused_k(const float* __restrict__ h2raw, __nv_bfloat16* __restrict__ a2) {
    size_t idx = (size_t)blockIdx.x * blockDim.x + threadIdx.x;
    if (idx >= (size_t)N_NODES * 512) return;
    int m = (int)(idx >> 9), k = (int)(idx & 511);
    float v = h2raw[idx] * g_scale[k] + g_shift[k];
    v = v >= 0.f ? v : SLOPE * v;
    __nv_bfloat16 hi = __float2bfloat16(v);
    __nv_bfloat16 lo = __float2bfloat16(v - __bfloat162float(hi));
    size_t base = (size_t)m * 1024;
    a2[base + k]       = hi;
    a2[base + 512 + k] = lo;
}

// ---------------- softmax ----------------
__global__ void softmax_k(const float* __restrict__ logits, float* __restrict__ out) {
    int r = blockIdx.x * blockDim.x + threadIdx.x;
    if (r >= N_NODES) return;
    float v[6];
    float m = -1e30f;
#pragma unroll
    for (int j = 0; j < 6; j++) { v[j] = logits[(size_t)r * 6 + j]; m = fmaxf(m, v[j]); }
    float ssum = 0.f;
#pragma unroll
    for (int j = 0; j < 6; j++) { v[j] = __expf(v[j] - m); ssum += v[j]; }
    float inv = 1.0f / ssum;
#pragma unroll
    for (int j = 0; j < 6; j++) out[(size_t)r * 6 + j] = v[j] * inv;
}

// ---------------- launch ----------------
static inline void* symp(const void* s) {
    void* p = nullptr;
    cudaGetSymbolAddress(&p, s);
    return p;
}

extern "C" void kernel_launch(void* const* d_in, const int* in_sizes, int n_in,
                              void* d_out, int out_size) {
    const float* x    = (const float*)d_in[0];
    const void*  ei   = d_in[1];
    const float* W1   = (const float*)d_in[2];
    const float* W2   = (const float*)d_in[4];
    const float* g1   = (const float*)d_in[6];
    const float* be1  = (const float*)d_in[7];
    const float* g2   = (const float*)d_in[8];
    const float* be2  = (const float*)d_in[9];
    const float* Wd1  = (const float*)d_in[10];
    const float* bd1  = (const float*)d_in[11];
    const float* Wd2  = (const float*)d_in[12];
    const float* bd2  = (const float*)d_in[13];
    float*       out  = (float*)d_out;

    unsigned char* arena = (unsigned char*)symp(g_arena);
    __nv_bfloat16* ga1 = (__nv_bfloat16*)arena;
    __nv_bfloat16* ga2 = (__nv_bfloat16*)(arena + (size_t)N_NODES * 256 * 2);
    __nv_bfloat16* a2  = (__nv_bfloat16*)arena;
    float* h1  = (float*)symp(g_h1);
    float* h2  = (float*)symp(g_h2);
    float* lg  = (float*)symp(g_logits);
    __nv_bfloat16* wd  = (__nv_bfloat16*)symp(g_wd);
    __nv_bfloat16* w1s = (__nv_bfloat16*)symp(g_w1s);
    __nv_bfloat16* w2s = (__nv_bfloat16*)symp(g_w2s);

    const int smemBytes = STAGE_B * NSTAGE;   // 184320
    cudaFuncSetAttribute(gemm_hilo_k<false>, cudaFuncAttributeMaxDynamicSharedMemorySize, smemBytes);
    cudaFuncSetAttribute(gemm_hilo_k<true>,  cudaFuncAttributeMaxDynamicSharedMemorySize, smemBytes);

    // edge conversion + CSR build
    detect_k<<<1, 256>>>((const unsigned long long*)ei);
    cvt_edges_k<<<(N_EDGES + 255) / 256, 256>>>(ei);
    cnt_zero_k<<<(N_NODES + 255) / 256, 256>>>();
    deg_count_k<<<(N_EDGES + 255) / 256, 256>>>();
    dinv_k<<<(N_NODES + 255) / 256, 256>>>();
    scan1_k<<<SCAN_NB, SCAN_CHUNK>>>();
    scan2_k<<<1, 32>>>();
    scan3_k<<<SCAN_NB, SCAN_CHUNK>>>();
    scatter_k<<<(N_EDGES + 255) / 256, 256>>>();

    // weight prep
    split_wt_k<<<(int)(((size_t)512 * 4096 + 255) / 256), 256>>>(Wd1, wd, 512, 4096);
    split_wt_k<<<(128 * 256 + 255) / 256, 256>>>(W1, w1s, 128, 256);
    split_wt_k<<<(256 * 512 + 255) / 256, 256>>>(W2, w2s, 256, 512);
    logits_init_k<<<(N_NODES * 6 + 255) / 256, 256>>>(bd2);

    // ---- layer 1 ----
    gather_split_k<128><<<(int)(((size_t)N_NODES * 32 + 255) / 256), 256>>>(x, ga1);
    {
        dim3 grid(256 / 256, (N_NODES + 127) / 128);
        gemm_hilo_k<false><<<grid, 256, smemBytes>>>(ga1, w1s, h1, nullptr, nullptr, N_NODES, 256, 128);
    }
    bn_zero_k<<<2, 256>>>(256);
    bn_reduce_k<256><<<512, 256>>>(h1);
    bn_scale_k<<<1, 256>>>(g1, be1, 256);
    bn_apply_k<256><<<(int)(((size_t)N_NODES * 256 + 255) / 256), 256>>>(h1);

    // ---- layer 2 ----
    gather_split_k<256><<<(int)(((size_t)N_NODES * 32 + 255) / 256), 256>>>(h1, ga2);
    {
        dim3 grid(512 / 256, (N_NODES + 127) / 128);
        gemm_hilo_k<false><<<grid, 256, smemBytes>>>(ga2, w2s, h2, nullptr, nullptr, N_NODES, 512, 256);
    }
    bn_zero_k<<<2, 256>>>(512);
    bn_reduce_k<512><<<512, 512>>>(h2);
    bn_scale_k<<<2, 256>>>(g2, be2, 512);

    // ---- fused BN-apply + leaky + split ----
    split_a_fused_k<<<(int)(((size_t)N_NODES * 512 + 255) / 256), 256>>>(h2, a2);

    // ---- dense1 + LeakyReLU + dense2 partials ----
    {
        dim3 grid(4096 / 256, (N_NODES + 127) / 128);
        gemm_hilo_k<true><<<grid, 256, smemBytes>>>(a2, wd, lg, bd1, Wd2, N_NODES, 4096, 512);
    }

    // ---- softmax ----
    softmax_k<<<(N_NODES + 255) / 256, 256>>>(lg, out);
}